// round 1
// baseline (speedup 1.0000x reference)
#include <cuda_runtime.h>

#define N_ATOMS   50000
#define N_BONDS   100000
#define MAX_NB    6
#define ATOM_FDIM 133
#define BOND_FDIM 147
#define HIDDEN    300
#define DEPTH     3

// ---------------- scratch (static device globals; no allocation) ----------------
__device__ float g_inp   [(size_t)N_BONDS * HIDDEN];  // f_bonds @ W_i (pre-activation)
__device__ float g_msg   [(size_t)N_BONDS * HIDDEN];  // current bond messages
__device__ float g_msg_in[(size_t)N_BONDS * HIDDEN];  // a_msg[b2a] - msg[b2revb]
__device__ float g_amsg  [(size_t)N_ATOMS * HIDDEN];  // per-atom neighbor sums
__device__ float g_ah    [(size_t)N_ATOMS * HIDDEN];  // atom hiddens

// ---------------- SGEMM: C = epilogue(A @ B) ----------------
// MODE 0: A = f_bonds [M x K];            g_inp = acc, g_msg = relu(acc)
// MODE 1: A = g_msg_in [M x K];           g_msg = relu(g_inp + acc)
// MODE 2: A = concat(f_atoms, g_amsg);    g_ah  = relu(acc + bias)
template<int MODE>
__global__ void __launch_bounds__(256) sgemm(
    const float* __restrict__ A, const float* __restrict__ B,
    const float* __restrict__ bias, int M, int N, int K, int KA)
{
    constexpr int BM = 128, BN = 128, BK = 8, TM = 8, TN = 8;
    __shared__ float As[BK][BM];
    __shared__ float Bs[BK][BN];

    const int tid = threadIdx.x;
    const int m0  = blockIdx.y * BM;
    const int n0  = blockIdx.x * BN;
    const int ty  = tid >> 4;        // 0..15
    const int tx  = tid & 15;        // 0..15

    float acc[TM][TN] = {};

    for (int k0 = 0; k0 < K; k0 += BK) {
        // load A tile (128 x 8), 4 elems/thread, stored transposed As[k][m]
        #pragma unroll
        for (int i = 0; i < 4; i++) {
            int li = tid * 4 + i;           // 0..1023
            int r  = li >> 3, c = li & 7;
            int gm = m0 + r, gk = k0 + c;
            float v = 0.f;
            if (gm < M && gk < K) {
                if (MODE == 0)      v = A[(size_t)gm * K + gk];
                else if (MODE == 1) v = g_msg_in[(size_t)gm * K + gk];
                else                v = (gk < KA) ? A[(size_t)gm * KA + gk]
                                                  : g_amsg[(size_t)gm * HIDDEN + (gk - KA)];
            }
            As[c][r] = v;
        }
        // load B tile (8 x 128), coalesced: each warp loads one full row
        #pragma unroll
        for (int i = 0; i < 4; i++) {
            int li = tid * 4 + i;
            int r  = li >> 7, c = li & 127;
            int gk = k0 + r, gn = n0 + c;
            Bs[r][c] = (gk < K && gn < N) ? B[(size_t)gk * N + gn] : 0.f;
        }
        __syncthreads();

        #pragma unroll
        for (int k = 0; k < BK; k++) {
            float ra[TM], rb[TN];
            #pragma unroll
            for (int i = 0; i < TM; i++) ra[i] = As[k][ty * TM + i];
            #pragma unroll
            for (int j = 0; j < TN; j++) rb[j] = Bs[k][tx * TN + j];
            #pragma unroll
            for (int i = 0; i < TM; i++)
                #pragma unroll
                for (int j = 0; j < TN; j++)
                    acc[i][j] = fmaf(ra[i], rb[j], acc[i][j]);
        }
        __syncthreads();
    }

    #pragma unroll
    for (int i = 0; i < TM; i++) {
        int gm = m0 + ty * TM + i;
        if (gm >= M) continue;
        #pragma unroll
        for (int j = 0; j < TN; j++) {
            int gn = n0 + tx * TN + j;
            if (gn >= N) continue;
            size_t o = (size_t)gm * N + gn;
            float v = acc[i][j];
            if (MODE == 0)      { g_inp[o] = v; g_msg[o] = fmaxf(v, 0.f); }
            else if (MODE == 1) { g_msg[o] = fmaxf(g_inp[o] + v, 0.f); }
            else                { g_ah[o]  = fmaxf(v + bias[gn], 0.f); }
        }
    }
}

// ---------------- a_message[a] = sum_k g_msg[a2b[a][k]] ----------------
__global__ void __launch_bounds__(256) atom_sum(const int* __restrict__ a2b)
{
    constexpr int HV = HIDDEN / 4;  // 75 float4 per row (1200B rows, 16B aligned)
    int idx = blockIdx.x * blockDim.x + threadIdx.x;
    if (idx >= N_ATOMS * HV) return;
    int a = idx / HV;
    int j = idx - a * HV;
    const float4* m4 = (const float4*)g_msg;
    float4 s = make_float4(0.f, 0.f, 0.f, 0.f);
    #pragma unroll
    for (int k = 0; k < MAX_NB; k++) {
        int b = __ldg(&a2b[a * MAX_NB + k]);
        float4 v = m4[(size_t)b * HV + j];
        s.x += v.x; s.y += v.y; s.z += v.z; s.w += v.w;
    }
    ((float4*)g_amsg)[idx] = s;
}

// ---------------- msg_in[m] = a_msg[b2a[m]] - msg[b2revb[m]] ----------------
__global__ void __launch_bounds__(256) bond_msg(
    const int* __restrict__ b2a, const int* __restrict__ b2revb)
{
    constexpr int HV = HIDDEN / 4;
    int idx = blockIdx.x * blockDim.x + threadIdx.x;
    if (idx >= N_BONDS * HV) return;
    int m = idx / HV;
    int j = idx - m * HV;
    float4 av = ((const float4*)g_amsg)[(size_t)__ldg(&b2a[m])    * HV + j];
    float4 rv = ((const float4*)g_msg )[(size_t)__ldg(&b2revb[m]) * HV + j];
    float4 o;
    o.x = av.x - rv.x; o.y = av.y - rv.y; o.z = av.z - rv.z; o.w = av.w - rv.w;
    ((float4*)g_msg_in)[idx] = o;
}

// ---------------- per-molecule mean (mol_id is sorted; deterministic) ----------------
__global__ void mol_mean(const int* __restrict__ mol_id, float* __restrict__ out)
{
    int mol = blockIdx.x;
    // lower_bound(mol)
    int lo = 0, hi = N_ATOMS;
    while (lo < hi) { int mid = (lo + hi) >> 1; if (mol_id[mid] < mol) lo = mid + 1; else hi = mid; }
    int start = lo;
    // lower_bound(mol+1)
    hi = N_ATOMS;
    while (lo < hi) { int mid = (lo + hi) >> 1; if (mol_id[mid] < mol + 1) lo = mid + 1; else hi = mid; }
    int end = lo;
    float inv = (end > start) ? 1.0f / (float)(end - start) : 0.0f;
    for (int j = threadIdx.x; j < HIDDEN; j += blockDim.x) {
        float s = 0.f;
        for (int a = start; a < end; a++) s += g_ah[(size_t)a * HIDDEN + j];
        out[(size_t)mol * HIDDEN + j] = s * inv;
    }
}

// ---------------- launch ----------------
extern "C" void kernel_launch(void* const* d_in, const int* in_sizes, int n_in,
                              void* d_out, int out_size)
{
    const float* f_atoms = (const float*)d_in[0];
    const float* f_bonds = (const float*)d_in[1];
    const int*   a2b     = (const int*)  d_in[2];
    const int*   b2a     = (const int*)  d_in[3];
    const int*   b2revb  = (const int*)  d_in[4];
    const int*   mol_id  = (const int*)  d_in[5];
    // n_mols may or may not be materialized as a 1-element tensor at index 6
    int wbase = (n_in >= 11 && in_sizes[6] == 1) ? 7 : 6;
    const float* W_i = (const float*)d_in[wbase + 0];
    const float* W_h = (const float*)d_in[wbase + 1];
    const float* W_o = (const float*)d_in[wbase + 2];
    const float* b_o = (const float*)d_in[wbase + 3];
    float* out = (float*)d_out;
    int n_mols = out_size / HIDDEN;

    constexpr int HV = HIDDEN / 4;
    dim3 blk(256);
    dim3 gb((HIDDEN + 127) / 128, (N_BONDS + 127) / 128);   // bond GEMMs
    dim3 ga((HIDDEN + 127) / 128, (N_ATOMS + 127) / 128);   // atom GEMM
    int atom_blocks = (N_ATOMS * HV + 255) / 256;
    int bond_blocks = (N_BONDS * HV + 255) / 256;

    // inp = f_bonds @ W_i ; message = relu(inp)
    sgemm<0><<<gb, blk>>>(f_bonds, W_i, nullptr, N_BONDS, HIDDEN, BOND_FDIM, 0);

    for (int d = 0; d < DEPTH - 1; d++) {
        atom_sum<<<atom_blocks, 256>>>(a2b);
        bond_msg<<<bond_blocks, 256>>>(b2a, b2revb);
        // message = relu(inp + msg_in @ W_h)
        sgemm<1><<<gb, blk>>>(nullptr, W_h, nullptr, N_BONDS, HIDDEN, HIDDEN, 0);
    }

    atom_sum<<<atom_blocks, 256>>>(a2b);
    // atom_hiddens = relu(concat(f_atoms, a_msg) @ W_o + b_o)
    sgemm<2><<<ga, blk>>>(f_atoms, W_o, b_o, N_ATOMS, HIDDEN, ATOM_FDIM + HIDDEN, ATOM_FDIM);

    mol_mean<<<n_mols, 128>>>(mol_id, out);
}

// round 4
// speedup vs baseline: 1.1331x; 1.1331x over previous
#include <cuda_runtime.h>
#include <cuda_bf16.h>
#include <cstdint>

#define N_ATOMS   50000
#define N_BONDS   100000
#define MAX_NB    6
#define ATOM_FDIM 133
#define BOND_FDIM 147
#define HIDDEN    300
#define DEPTH     3

// ---------------- scratch (static device globals; no allocation) ----------------
__device__ float g_inp   [(size_t)N_BONDS * HIDDEN];
__device__ float g_msg   [(size_t)N_BONDS * HIDDEN];
__device__ float g_msg_in[(size_t)N_BONDS * HIDDEN];
__device__ float g_amsg  [(size_t)N_ATOMS * HIDDEN];
__device__ float g_ah    [(size_t)N_ATOMS * HIDDEN];

// ---------------- helpers ----------------
__device__ __forceinline__ uint32_t smem_u32(const void* p) {
    uint32_t a;
    asm("{ .reg .u64 t; cvta.to.shared.u64 t, %1; cvt.u32.u64 %0, t; }" : "=r"(a) : "l"(p));
    return a;
}
__device__ __forceinline__ void ldsm4(uint32_t* r, uint32_t addr) {
    asm volatile("ldmatrix.sync.aligned.m8n8.x4.shared.b16 {%0,%1,%2,%3}, [%4];"
        : "=r"(r[0]), "=r"(r[1]), "=r"(r[2]), "=r"(r[3]) : "r"(addr));
}
__device__ __forceinline__ void ldsm4t(uint32_t* r, uint32_t addr) {
    asm volatile("ldmatrix.sync.aligned.m8n8.x4.trans.shared.b16 {%0,%1,%2,%3}, [%4];"
        : "=r"(r[0]), "=r"(r[1]), "=r"(r[2]), "=r"(r[3]) : "r"(addr));
}
__device__ __forceinline__ void mma16816(float* c, const uint32_t* a, uint32_t b0, uint32_t b1) {
    asm volatile("mma.sync.aligned.m16n8k16.row.col.f32.bf16.bf16.f32 "
        "{%0,%1,%2,%3}, {%4,%5,%6,%7}, {%8,%9}, {%0,%1,%2,%3};"
        : "+f"(c[0]), "+f"(c[1]), "+f"(c[2]), "+f"(c[3])
        : "r"(a[0]), "r"(a[1]), "r"(a[2]), "r"(a[3]), "r"(b0), "r"(b1));
}

constexpr int SA = 40;    // A smem row stride (bf16 elems), 128 rows x 32 cols used
constexpr int SB = 136;   // B smem row stride (bf16 elems), 32 rows x 128 cols used

template<int MODE>
__device__ __forceinline__ float fetchA(const float* __restrict__ A, int gm, int gk, int M, int K) {
    if (gm >= M || gk >= K) return 0.f;
    if (MODE == 0) return A[(size_t)gm * BOND_FDIM + gk];
    if (MODE == 1) return g_msg_in[(size_t)gm * HIDDEN + gk];
    return (gk < ATOM_FDIM) ? A[(size_t)gm * ATOM_FDIM + gk]
                            : g_amsg[(size_t)gm * HIDDEN + (gk - ATOM_FDIM)];
}

// ---------------- HMMA GEMM ----------------
// C[M x 300] = epilogue(A[M x K] @ B[K x 300])
// BM=128, BN=128, BK=32; 256 threads (8 warps: 4 m-warps x 2 n-warps)
// MODE 0: A=f_bonds;                g_inp=acc, g_msg=relu(acc)
// MODE 1: A=g_msg_in;               g_msg=relu(g_inp+acc)
// MODE 2: A=concat(f_atoms,g_amsg); g_ah =relu(acc+bias)
template<int MODE>
__global__ void __launch_bounds__(256) gemm_mma(
    const float* __restrict__ A, const float* __restrict__ B,
    const float* __restrict__ bias, int M, int K)
{
    __shared__ __align__(16) ushort sAh[128 * SA];
    __shared__ __align__(16) ushort sAl[128 * SA];
    __shared__ __align__(16) ushort sBh[32 * SB];
    __shared__ __align__(16) ushort sBl[32 * SB];

    const int tid = threadIdx.x, lane = tid & 31, wid = tid >> 5;
    const int m0 = blockIdx.y * 128, n0 = blockIdx.x * 128;
    const int wm = wid & 3, wn = wid >> 2;   // warp tile: 32 m x 64 n

    float acc[2][8][4];
    #pragma unroll
    for (int i = 0; i < 2; i++)
        #pragma unroll
        for (int j = 0; j < 8; j++)
            #pragma unroll
            for (int q = 0; q < 4; q++) acc[i][j][q] = 0.f;

    const int niter = (K + 31) / 32;

    for (int it = 0; it < niter; it++) {
        const int k0 = it * 32;
        // ---- load A tile [128 x 32], coalesced, hi/lo bf16 split ----
        #pragma unroll
        for (int i = 0; i < 16; i++) {
            int idx = i * 256 + tid;          // 0..4095
            int r = idx >> 5, c = idx & 31;
            float v = fetchA<MODE>(A, m0 + r, k0 + c, M, K);
            __nv_bfloat16 h = __float2bfloat16(v);
            __nv_bfloat16 l = __float2bfloat16(v - __bfloat162float(h));
            sAh[r * SA + c] = __bfloat16_as_ushort(h);
            sAl[r * SA + c] = __bfloat16_as_ushort(l);
        }
        // ---- load B tile [32 x 128], coalesced ----
        #pragma unroll
        for (int i = 0; i < 16; i++) {
            int idx = i * 256 + tid;          // 0..4095
            int r = idx >> 7, c = idx & 127;
            int gk = k0 + r, gn = n0 + c;
            float v = (gk < K && gn < HIDDEN) ? B[(size_t)gk * HIDDEN + gn] : 0.f;
            __nv_bfloat16 h = __float2bfloat16(v);
            __nv_bfloat16 l = __float2bfloat16(v - __bfloat162float(h));
            sBh[r * SB + c] = __bfloat16_as_ushort(h);
            sBl[r * SB + c] = __bfloat16_as_ushort(l);
        }
        __syncthreads();

        // ---- MMA: 2 k-steps of 16 ----
        #pragma unroll
        for (int ks = 0; ks < 2; ks++) {
            uint32_t ah[2][4], al[2][4], bh[4][4], bl[4][4];
            const int arow = wm * 32 + (lane & 15);
            const int acol = ks * 16 + (lane >> 4) * 8;
            #pragma unroll
            for (int mi = 0; mi < 2; mi++) {
                uint32_t offA = smem_u32(&sAh[(arow + mi * 16) * SA + acol]);
                uint32_t offAl = smem_u32(&sAl[(arow + mi * 16) * SA + acol]);
                ldsm4(ah[mi], offA);
                ldsm4(al[mi], offAl);
            }
            const int bkrow = ks * 16 + (lane & 15);
            const int bncol = wn * 64 + (lane >> 4) * 8;
            #pragma unroll
            for (int ni = 0; ni < 4; ni++) {
                uint32_t offB = smem_u32(&sBh[bkrow * SB + bncol + ni * 16]);
                uint32_t offBl = smem_u32(&sBl[bkrow * SB + bncol + ni * 16]);
                ldsm4t(bh[ni], offB);
                ldsm4t(bl[ni], offBl);
            }
            #pragma unroll
            for (int mi = 0; mi < 2; mi++) {
                #pragma unroll
                for (int p = 0; p < 4; p++) {
                    mma16816(acc[mi][2*p],   ah[mi], bh[p][0], bh[p][1]);
                    mma16816(acc[mi][2*p],   ah[mi], bl[p][0], bl[p][1]);
                    mma16816(acc[mi][2*p],   al[mi], bh[p][0], bh[p][1]);
                    mma16816(acc[mi][2*p+1], ah[mi], bh[p][2], bh[p][3]);
                    mma16816(acc[mi][2*p+1], ah[mi], bl[p][2], bl[p][3]);
                    mma16816(acc[mi][2*p+1], al[mi], bh[p][2], bh[p][3]);
                }
            }
        }
        __syncthreads();
    }

    // ---- epilogue (scalar, fully guarded) ----
    #pragma unroll
    for (int mi = 0; mi < 2; mi++) {
        #pragma unroll
        for (int t8 = 0; t8 < 8; t8++) {
            int col = n0 + wn * 64 + t8 * 8 + (lane & 3) * 2;
            #pragma unroll
            for (int h = 0; h < 2; h++) {
                int r = m0 + wm * 32 + mi * 16 + (lane >> 2) + h * 8;
                if (r >= M) continue;
                float v0 = acc[mi][t8][2*h], v1 = acc[mi][t8][2*h+1];
                #pragma unroll
                for (int e = 0; e < 2; e++) {
                    int cn = col + e;
                    if (cn >= HIDDEN) continue;
                    float v = e ? v1 : v0;
                    size_t o = (size_t)r * HIDDEN + cn;
                    if (MODE == 0)      { g_inp[o] = v; g_msg[o] = fmaxf(v, 0.f); }
                    else if (MODE == 1) { g_msg[o] = fmaxf(g_inp[o] + v, 0.f); }
                    else                { g_ah[o]  = fmaxf(v + bias[cn], 0.f); }
                }
            }
        }
    }
}

// ---------------- a_message[a] = sum_k g_msg[a2b[a][k]] ----------------
__global__ void __launch_bounds__(256) atom_sum(const int* __restrict__ a2b)
{
    constexpr int HV = HIDDEN / 4;
    int idx = blockIdx.x * blockDim.x + threadIdx.x;
    if (idx >= N_ATOMS * HV) return;
    int a = idx / HV;
    int j = idx - a * HV;
    const float4* m4 = (const float4*)g_msg;
    float4 s = make_float4(0.f, 0.f, 0.f, 0.f);
    #pragma unroll
    for (int k = 0; k < MAX_NB; k++) {
        int b = __ldg(&a2b[a * MAX_NB + k]);
        float4 v = m4[(size_t)b * HV + j];
        s.x += v.x; s.y += v.y; s.z += v.z; s.w += v.w;
    }
    ((float4*)g_amsg)[idx] = s;
}

// ---------------- msg_in[m] = a_msg[b2a[m]] - msg[b2revb[m]] ----------------
__global__ void __launch_bounds__(256) bond_msg(
    const int* __restrict__ b2a, const int* __restrict__ b2revb)
{
    constexpr int HV = HIDDEN / 4;
    int idx = blockIdx.x * blockDim.x + threadIdx.x;
    if (idx >= N_BONDS * HV) return;
    int m = idx / HV;
    int j = idx - m * HV;
    float4 av = ((const float4*)g_amsg)[(size_t)__ldg(&b2a[m])    * HV + j];
    float4 rv = ((const float4*)g_msg )[(size_t)__ldg(&b2revb[m]) * HV + j];
    float4 o;
    o.x = av.x - rv.x; o.y = av.y - rv.y; o.z = av.z - rv.z; o.w = av.w - rv.w;
    ((float4*)g_msg_in)[idx] = o;
}

// ---------------- per-molecule mean (mol_id sorted; deterministic) ----------------
__global__ void mol_mean(const int* __restrict__ mol_id, float* __restrict__ out)
{
    int mol = blockIdx.x;
    int lo = 0, hi = N_ATOMS;
    while (lo < hi) { int mid = (lo + hi) >> 1; if (mol_id[mid] < mol) lo = mid + 1; else hi = mid; }
    int start = lo;
    hi = N_ATOMS;
    while (lo < hi) { int mid = (lo + hi) >> 1; if (mol_id[mid] < mol + 1) lo = mid + 1; else hi = mid; }
    int end = lo;
    float inv = (end > start) ? 1.0f / (float)(end - start) : 0.0f;
    for (int j = threadIdx.x; j < HIDDEN; j += blockDim.x) {
        float s = 0.f;
        for (int a = start; a < end; a++) s += g_ah[(size_t)a * HIDDEN + j];
        out[(size_t)mol * HIDDEN + j] = s * inv;
    }
}

// ---------------- launch ----------------
extern "C" void kernel_launch(void* const* d_in, const int* in_sizes, int n_in,
                              void* d_out, int out_size)
{
    const float* f_atoms = (const float*)d_in[0];
    const float* f_bonds = (const float*)d_in[1];
    const int*   a2b     = (const int*)  d_in[2];
    const int*   b2a     = (const int*)  d_in[3];
    const int*   b2revb  = (const int*)  d_in[4];
    const int*   mol_id  = (const int*)  d_in[5];
    int wbase = (n_in >= 11 && in_sizes[6] == 1) ? 7 : 6;
    const float* W_i = (const float*)d_in[wbase + 0];
    const float* W_h = (const float*)d_in[wbase + 1];
    const float* W_o = (const float*)d_in[wbase + 2];
    const float* b_o = (const float*)d_in[wbase + 3];
    float* out = (float*)d_out;
    int n_mols = out_size / HIDDEN;

    constexpr int HV = HIDDEN / 4;
    dim3 gb(3, (N_BONDS + 127) / 128);
    dim3 ga(3, (N_ATOMS + 127) / 128);
    int atom_blocks = (N_ATOMS * HV + 255) / 256;
    int bond_blocks = (N_BONDS * HV + 255) / 256;

    gemm_mma<0><<<gb, 256>>>(f_bonds, W_i, nullptr, N_BONDS, BOND_FDIM);

    for (int d = 0; d < DEPTH - 1; d++) {
        atom_sum<<<atom_blocks, 256>>>(a2b);
        bond_msg<<<bond_blocks, 256>>>(b2a, b2revb);
        gemm_mma<1><<<gb, 256>>>(nullptr, W_h, nullptr, N_BONDS, HIDDEN);
    }

    atom_sum<<<atom_blocks, 256>>>(a2b);
    gemm_mma<2><<<ga, 256>>>(f_atoms, W_o, b_o, N_ATOMS, ATOM_FDIM + HIDDEN);

    mol_mean<<<n_mols, 128>>>(mol_id, out);
}

// round 6
// speedup vs baseline: 2.3198x; 2.0473x over previous
#include <cuda_runtime.h>
#include <cuda_bf16.h>
#include <cstdint>

#define N_ATOMS   50000
#define N_BONDS   100000
#define MAX_NB    6
#define ATOM_FDIM 133
#define BOND_FDIM 147
#define HIDDEN    300
#define DEPTH     3

// padded K per GEMM (multiples of 32)
#define K0P 160   // bond_fdim 147 -> 160
#define K1P 320   // hidden 300 -> 320
#define K2P 448   // 300 + 133 = 433 -> 448  (A order: [amsg | f_atoms | pad])
#define NBP 384   // padded N for weight buffers

// ---------------- scratch (static device globals; no allocation) ----------------
__device__ float  g_inp [(size_t)N_BONDS * HIDDEN];
__device__ float  g_msg [(size_t)N_BONDS * HIDDEN];
__device__ float  g_amsg[(size_t)N_ATOMS * HIDDEN];
__device__ float  g_ah  [(size_t)N_ATOMS * HIDDEN];
__device__ __align__(16) ushort gA0h[(size_t)N_BONDS * K0P], gA0l[(size_t)N_BONDS * K0P];
__device__ __align__(16) ushort gA1h[(size_t)N_BONDS * K1P], gA1l[(size_t)N_BONDS * K1P];
__device__ __align__(16) ushort gA2h[(size_t)N_ATOMS * K2P], gA2l[(size_t)N_ATOMS * K2P];
__device__ __align__(16) ushort gWh [(size_t)K2P * NBP],     gWl [(size_t)K2P * NBP];

// ---------------- helpers ----------------
__device__ __forceinline__ uint32_t smem_u32(const void* p) {
    uint32_t a;
    asm("{ .reg .u64 t; cvta.to.shared.u64 t, %1; cvt.u32.u64 %0, t; }" : "=r"(a) : "l"(p));
    return a;
}
__device__ __forceinline__ void ldsm4(uint32_t* r, uint32_t addr) {
    asm volatile("ldmatrix.sync.aligned.m8n8.x4.shared.b16 {%0,%1,%2,%3}, [%4];"
        : "=r"(r[0]), "=r"(r[1]), "=r"(r[2]), "=r"(r[3]) : "r"(addr));
}
__device__ __forceinline__ void ldsm4t(uint32_t* r, uint32_t addr) {
    asm volatile("ldmatrix.sync.aligned.m8n8.x4.trans.shared.b16 {%0,%1,%2,%3}, [%4];"
        : "=r"(r[0]), "=r"(r[1]), "=r"(r[2]), "=r"(r[3]) : "r"(addr));
}
__device__ __forceinline__ void mma16816(float* c, const uint32_t* a, uint32_t b0, uint32_t b1) {
    asm volatile("mma.sync.aligned.m16n8k16.row.col.f32.bf16.bf16.f32 "
        "{%0,%1,%2,%3}, {%4,%5,%6,%7}, {%8,%9}, {%0,%1,%2,%3};"
        : "+f"(c[0]), "+f"(c[1]), "+f"(c[2]), "+f"(c[3])
        : "r"(a[0]), "r"(a[1]), "r"(a[2]), "r"(a[3]), "r"(b0), "r"(b1));
}
__device__ __forceinline__ void cp16(uint32_t dst, const void* src, bool pred) {
    asm volatile("cp.async.cg.shared.global [%0], [%1], 16, %2;"
        :: "r"(dst), "l"(src), "r"(pred ? 16 : 0) : "memory");
}
__device__ __forceinline__ void split_bf16(float v, ushort& h, ushort& l) {
    __nv_bfloat16 hb = __float2bfloat16(v);
    __nv_bfloat16 lb = __float2bfloat16(v - __bfloat162float(hb));
    h = __bfloat16_as_ushort(hb); l = __bfloat16_as_ushort(lb);
}

// ---------------- smem layout ----------------
constexpr int SA = 40, SB = 136;                 // bf16 elem strides (ldmatrix pad)
constexpr int A_STG = 128 * SA * 2;              // 10240 B
constexpr int B_STG = 32 * SB * 2;               // 8704 B
constexpr int OFF_AH = 0;
constexpr int OFF_AL = 2 * A_STG;                // 20480
constexpr int OFF_BH = 4 * A_STG;                // 40960
constexpr int OFF_BL = OFF_BH + 2 * B_STG;       // 58368
constexpr int SMEM_BYTES = OFF_BL + 2 * B_STG;   // 75776

// ---------------- pipelined bf16 HMMA GEMM ----------------
// C[M x 300] = epi(A @ B); A/B bf16 hi/lo device-global buffers picked by MODE.
// BM=128, BN=128, BK=32; 256 threads (8 warps: 4 m-warps x 2 n-warps).
// MODE 0: A=gA0 (K=160); g_inp=acc, g_msg=relu(acc)
// MODE 1: A=gA1 (K=320); g_msg=relu(g_inp+acc)
// MODE 2: A=gA2 (K=448); g_ah =relu(acc+bias)
template<int MODE>
__global__ void __launch_bounds__(256) gemm_bf16(const float* __restrict__ bias, int M)
{
    constexpr int K = (MODE == 0) ? K0P : (MODE == 1) ? K1P : K2P;
    const ushort* __restrict__ Ahi = (MODE == 0) ? gA0h : (MODE == 1) ? gA1h : gA2h;
    const ushort* __restrict__ Alo = (MODE == 0) ? gA0l : (MODE == 1) ? gA1l : gA2l;

    extern __shared__ char sm[];
    const uint32_t sb = smem_u32(sm);
    const int tid = threadIdx.x, lane = tid & 31, wid = tid >> 5;
    const int m0 = blockIdx.y * 128, n0 = blockIdx.x * 128;
    const int wm = wid & 3, wn = wid >> 2;

    float acc[2][8][4];
    #pragma unroll
    for (int i = 0; i < 2; i++)
        #pragma unroll
        for (int j = 0; j < 8; j++)
            #pragma unroll
            for (int q = 0; q < 4; q++) acc[i][j][q] = 0.f;

    constexpr int niter = K / 32;

    auto issue = [&](int it) {
        const int st = it & 1;
        const int k0 = it * 32;
        // A: 512 x 16B chunks per array (row = 4 chunks of 8 bf16)
        #pragma unroll
        for (int i = 0; i < 2; i++) {
            int q = i * 256 + tid;
            int row = q >> 2, c16 = q & 3;
            int gm = m0 + row;
            bool p = gm < M;
            size_t so = (size_t)(p ? gm : 0) * K + k0 + c16 * 8;
            uint32_t doff = (uint32_t)(row * SA + c16 * 8) * 2;
            cp16(sb + OFF_AH + st * A_STG + doff, Ahi + so, p);
            cp16(sb + OFF_AL + st * A_STG + doff, Alo + so, p);
        }
        // B: 512 x 16B chunks per array (rows k0..k0+31 all < K; cols padded to NBP)
        #pragma unroll
        for (int i = 0; i < 2; i++) {
            int q = i * 256 + tid;
            int row = q >> 4, c16 = q & 15;
            size_t so = (size_t)(k0 + row) * NBP + n0 + c16 * 8;
            uint32_t doff = (uint32_t)(row * SB + c16 * 8) * 2;
            cp16(sb + OFF_BH + st * B_STG + doff, gWh + so, true);
            cp16(sb + OFF_BL + st * B_STG + doff, gWl + so, true);
        }
        asm volatile("cp.async.commit_group;" ::: "memory");
    };

    issue(0);
    for (int it = 0; it < niter; it++) {
        if (it + 1 < niter) {
            issue(it + 1);
            asm volatile("cp.async.wait_group 1;" ::: "memory");
        } else {
            asm volatile("cp.async.wait_group 0;" ::: "memory");
        }
        __syncthreads();

        const int st = it & 1;
        const uint32_t aH = sb + OFF_AH + st * A_STG, aL = sb + OFF_AL + st * A_STG;
        const uint32_t bH = sb + OFF_BH + st * B_STG, bL = sb + OFF_BL + st * B_STG;
        #pragma unroll
        for (int ks = 0; ks < 2; ks++) {
            uint32_t ah[2][4], al[2][4], bh[4][4], bl[4][4];
            const int arow = wm * 32 + (lane & 15);
            const int acol = ks * 16 + (lane >> 4) * 8;
            #pragma unroll
            for (int mi = 0; mi < 2; mi++) {
                uint32_t off = (uint32_t)((arow + mi * 16) * SA + acol) * 2;
                ldsm4(ah[mi], aH + off);
                ldsm4(al[mi], aL + off);
            }
            const int bkrow = ks * 16 + (lane & 15);
            const int bncol = wn * 64 + (lane >> 4) * 8;
            #pragma unroll
            for (int ni = 0; ni < 4; ni++) {
                uint32_t off = (uint32_t)(bkrow * SB + bncol + ni * 16) * 2;
                ldsm4t(bh[ni], bH + off);
                ldsm4t(bl[ni], bL + off);
            }
            #pragma unroll
            for (int mi = 0; mi < 2; mi++) {
                #pragma unroll
                for (int p = 0; p < 4; p++) {
                    mma16816(acc[mi][2*p],   ah[mi], bh[p][0], bh[p][1]);
                    mma16816(acc[mi][2*p],   ah[mi], bl[p][0], bl[p][1]);
                    mma16816(acc[mi][2*p],   al[mi], bh[p][0], bh[p][1]);
                    mma16816(acc[mi][2*p+1], ah[mi], bh[p][2], bh[p][3]);
                    mma16816(acc[mi][2*p+1], ah[mi], bl[p][2], bl[p][3]);
                    mma16816(acc[mi][2*p+1], al[mi], bh[p][2], bh[p][3]);
                }
            }
        }
        __syncthreads();
    }

    // ---- epilogue ----
    #pragma unroll
    for (int mi = 0; mi < 2; mi++) {
        #pragma unroll
        for (int t8 = 0; t8 < 8; t8++) {
            int col = n0 + wn * 64 + t8 * 8 + (lane & 3) * 2;
            #pragma unroll
            for (int h = 0; h < 2; h++) {
                int r = m0 + wm * 32 + mi * 16 + (lane >> 2) + h * 8;
                if (r >= M) continue;
                #pragma unroll
                for (int e = 0; e < 2; e++) {
                    int cn = col + e;
                    if (cn >= HIDDEN) continue;
                    float v = acc[mi][t8][2*h + e];
                    size_t o = (size_t)r * HIDDEN + cn;
                    if (MODE == 0)      { g_inp[o] = v; g_msg[o] = fmaxf(v, 0.f); }
                    else if (MODE == 1) { g_msg[o] = fmaxf(g_inp[o] + v, 0.f); }
                    else                { g_ah[o]  = fmaxf(v + bias[cn], 0.f); }
                }
            }
        }
    }
}

// ---------------- weight converters: W[K x 300] fp32 -> gW hi/lo [Kp x NBP] ----------------
__global__ void conv_w(const float* __restrict__ W, int K, int Kp)
{
    int idx = blockIdx.x * blockDim.x + threadIdx.x;
    if (idx >= Kp * NBP) return;
    int k = idx / NBP, n = idx - k * NBP;
    float v = (k < K && n < HIDDEN) ? W[(size_t)k * HIDDEN + n] : 0.f;
    ushort h, l; split_bf16(v, h, l);
    gWh[idx] = h; gWl[idx] = l;
}
// W_o remap: row k<300 -> W_o[133+k] (amsg part); 300<=k<433 -> W_o[k-300] (f_atoms)
__global__ void conv_w_o(const float* __restrict__ W)
{
    int idx = blockIdx.x * blockDim.x + threadIdx.x;
    if (idx >= K2P * NBP) return;
    int k = idx / NBP, n = idx - k * NBP;
    int src = (k < HIDDEN) ? (ATOM_FDIM + k) : (k < HIDDEN + ATOM_FDIM ? k - HIDDEN : -1);
    float v = (src >= 0 && n < HIDDEN) ? W[(size_t)src * HIDDEN + n] : 0.f;
    ushort h, l; split_bf16(v, h, l);
    gWh[idx] = h; gWl[idx] = l;
}

// ---------------- f_bonds -> gA0 ----------------
__global__ void conv_fbonds(const float* __restrict__ F)
{
    int idx = blockIdx.x * blockDim.x + threadIdx.x;
    if (idx >= N_BONDS * K0P) return;
    int r = idx / K0P, c = idx - r * K0P;
    float v = (c < BOND_FDIM) ? F[(size_t)r * BOND_FDIM + c] : 0.f;
    ushort h, l; split_bf16(v, h, l);
    gA0h[idx] = h; gA0l[idx] = l;
}
// ---------------- f_atoms -> gA2 cols [300..447] (133 feats + 15 pad) ----------------
__global__ void conv_fatoms(const float* __restrict__ F)
{
    constexpr int C = K2P - HIDDEN;  // 148
    int idx = blockIdx.x * blockDim.x + threadIdx.x;
    if (idx >= N_ATOMS * C) return;
    int a = idx / C, c = idx - a * C;
    float v = (c < ATOM_FDIM) ? F[(size_t)a * ATOM_FDIM + c] : 0.f;
    ushort h, l; split_bf16(v, h, l);
    size_t o = (size_t)a * K2P + HIDDEN + c;
    gA2h[o] = h; gA2l[o] = l;
}

// ---------------- atom_sum: a_msg[a] = sum_k g_msg[a2b[a][k]] ----------------
// FIN=false -> g_amsg fp32; FIN=true -> bf16 hi/lo into gA2 cols [0..300)
template<bool FIN>
__global__ void __launch_bounds__(256) atom_sum(const int* __restrict__ a2b)
{
    constexpr int HV = HIDDEN / 4;
    int idx = blockIdx.x * blockDim.x + threadIdx.x;
    if (idx >= N_ATOMS * HV) return;
    int a = idx / HV;
    int j = idx - a * HV;
    const float4* m4 = (const float4*)g_msg;
    float4 s = make_float4(0.f, 0.f, 0.f, 0.f);
    #pragma unroll
    for (int k = 0; k < MAX_NB; k++) {
        int b = __ldg(&a2b[a * MAX_NB + k]);
        float4 v = m4[(size_t)b * HV + j];
        s.x += v.x; s.y += v.y; s.z += v.z; s.w += v.w;
    }
    if (!FIN) {
        ((float4*)g_amsg)[idx] = s;
    } else {
        ushort4 hh, ll;
        split_bf16(s.x, hh.x, ll.x); split_bf16(s.y, hh.y, ll.y);
        split_bf16(s.z, hh.z, ll.z); split_bf16(s.w, hh.w, ll.w);
        size_t o = (size_t)a * K2P + j * 4;
        *(ushort4*)&gA2h[o] = hh;
        *(ushort4*)&gA2l[o] = ll;
    }
}

// ---------------- bond_msg: gA1 = split_bf16(a_msg[b2a] - msg[b2revb]) ----------------
__global__ void __launch_bounds__(256) bond_msg(
    const int* __restrict__ b2a, const int* __restrict__ b2revb)
{
    constexpr int G = K1P / 4;   // 80 groups of 4 cols
    int idx = blockIdx.x * blockDim.x + threadIdx.x;
    if (idx >= N_BONDS * G) return;
    int m = idx / G;
    int g = idx - m * G;
    size_t o = (size_t)m * K1P + g * 4;
    if (g < HIDDEN / 4) {
        float4 av = ((const float4*)g_amsg)[(size_t)__ldg(&b2a[m])    * (HIDDEN/4) + g];
        float4 rv = ((const float4*)g_msg )[(size_t)__ldg(&b2revb[m]) * (HIDDEN/4) + g];
        float4 d = make_float4(av.x - rv.x, av.y - rv.y, av.z - rv.z, av.w - rv.w);
        ushort4 hh, ll;
        split_bf16(d.x, hh.x, ll.x); split_bf16(d.y, hh.y, ll.y);
        split_bf16(d.z, hh.z, ll.z); split_bf16(d.w, hh.w, ll.w);
        *(ushort4*)&gA1h[o] = hh;
        *(ushort4*)&gA1l[o] = ll;
    } else {
        ushort4 z = make_ushort4(0, 0, 0, 0);
        *(ushort4*)&gA1h[o] = z;
        *(ushort4*)&gA1l[o] = z;
    }
}

// ---------------- per-molecule mean (mol_id sorted; deterministic) ----------------
__global__ void mol_mean(const int* __restrict__ mol_id, float* __restrict__ out)
{
    int mol = blockIdx.x;
    int lo = 0, hi = N_ATOMS;
    while (lo < hi) { int mid = (lo + hi) >> 1; if (mol_id[mid] < mol) lo = mid + 1; else hi = mid; }
    int start = lo;
    hi = N_ATOMS;
    while (lo < hi) { int mid = (lo + hi) >> 1; if (mol_id[mid] < mol + 1) lo = mid + 1; else hi = mid; }
    int end = lo;
    float inv = (end > start) ? 1.0f / (float)(end - start) : 0.0f;
    for (int j = threadIdx.x; j < HIDDEN; j += blockDim.x) {
        float s = 0.f;
        for (int a = start; a < end; a++) s += g_ah[(size_t)a * HIDDEN + j];
        out[(size_t)mol * HIDDEN + j] = s * inv;
    }
}

// ---------------- launch ----------------
extern "C" void kernel_launch(void* const* d_in, const int* in_sizes, int n_in,
                              void* d_out, int out_size)
{
    const float* f_atoms = (const float*)d_in[0];
    const float* f_bonds = (const float*)d_in[1];
    const int*   a2b     = (const int*)  d_in[2];
    const int*   b2a     = (const int*)  d_in[3];
    const int*   b2revb  = (const int*)  d_in[4];
    const int*   mol_id  = (const int*)  d_in[5];
    int wbase = (n_in >= 11 && in_sizes[6] == 1) ? 7 : 6;
    const float* W_i = (const float*)d_in[wbase + 0];
    const float* W_h = (const float*)d_in[wbase + 1];
    const float* W_o = (const float*)d_in[wbase + 2];
    const float* b_o = (const float*)d_in[wbase + 3];
    float* out = (float*)d_out;
    int n_mols = out_size / HIDDEN;

    cudaFuncSetAttribute(gemm_bf16<0>, cudaFuncAttributeMaxDynamicSharedMemorySize, SMEM_BYTES);
    cudaFuncSetAttribute(gemm_bf16<1>, cudaFuncAttributeMaxDynamicSharedMemorySize, SMEM_BYTES);
    cudaFuncSetAttribute(gemm_bf16<2>, cudaFuncAttributeMaxDynamicSharedMemorySize, SMEM_BYTES);

    dim3 gb(3, (N_BONDS + 127) / 128);
    dim3 ga(3, (N_ATOMS + 127) / 128);
    int atom_blocks = (N_ATOMS * (HIDDEN/4) + 255) / 256;
    int bond_blocks = (N_BONDS * (K1P/4) + 255) / 256;

    // GEMM 0: message = relu(inp = f_bonds @ W_i)
    conv_w<<<(K0P * NBP + 255) / 256, 256>>>(W_i, BOND_FDIM, K0P);
    conv_fbonds<<<((size_t)N_BONDS * K0P + 255) / 256, 256>>>(f_bonds);
    gemm_bf16<0><<<gb, 256, SMEM_BYTES>>>(nullptr, N_BONDS);

    // depth loop: message = relu(inp + (a_msg[b2a]-msg[b2revb]) @ W_h)
    conv_w<<<(K1P * NBP + 255) / 256, 256>>>(W_h, HIDDEN, K1P);
    for (int d = 0; d < DEPTH - 1; d++) {
        atom_sum<false><<<atom_blocks, 256>>>(a2b);
        bond_msg<<<bond_blocks, 256>>>(b2a, b2revb);
        gemm_bf16<1><<<gb, 256, SMEM_BYTES>>>(nullptr, N_BONDS);
    }

    // readout: atom_hiddens = relu(concat @ W_o + b_o)
    atom_sum<true><<<atom_blocks, 256>>>(a2b);
    conv_fatoms<<<((size_t)N_ATOMS * (K2P - HIDDEN) + 255) / 256, 256>>>(f_atoms);
    conv_w_o<<<(K2P * NBP + 255) / 256, 256>>>(W_o);
    gemm_bf16<2><<<ga, 256, SMEM_BYTES>>>(b_o, N_ATOMS);

    mol_mean<<<n_mols, 128>>>(mol_id, out);
}